// round 4
// baseline (speedup 1.0000x reference)
#include <cuda_runtime.h>
#include <cuda_fp16.h>
#include <cstdint>

// ---------------- problem constants ----------------
#define N_INPUT   1024
#define N_OUTPUT  512
#define BATCHC    32
#define T_STEPS   100
#define TB_PAD    104                    // padded per-b t-length (mult of 8)
#define K_PAD     (BATCHC * TB_PAD)      // 3328
#define K_SPLIT   2
#define K_PART    (K_PAD / K_SPLIT)      // 1664
#define CHUNK     64                     // k per pipeline stage
#define NCHUNKS   (K_PART / CHUNK)       // 26

#define LR_LTP_F  (1e-4f)
#define LR_LTD_F  (-1e-4f)
#define DECAY     (0.951229424500714f)   // exp(-1/20)

#define PRETR_OFF  (N_OUTPUT * N_INPUT)
#define POSTTR_OFF (PRETR_OFF + BATCHC * N_INPUT)

// ---------------- device scratch (no allocations) ----------------
static __device__ __align__(16) __half g_A0[N_OUTPUT * K_PAD]; // postS  [o][k]
static __device__ __align__(16) __half g_A1[N_OUTPUT * K_PAD]; // postTr [o][k]
static __device__ __align__(16) __half g_B0[N_INPUT  * K_PAD]; // preTr  [i][k]
static __device__ __align__(16) __half g_B1[N_INPUT  * K_PAD]; // preS   [i][k]
static __device__ float g_P0[K_SPLIT * N_OUTPUT * N_INPUT];    // ltp partials
static __device__ float g_P1[K_SPLIT * N_OUTPUT * N_INPUT];    // ltd partials

// ---------------- helpers ----------------
__device__ __forceinline__ uint32_t smem_u32(const void* p) {
    uint32_t a;
    asm("{ .reg .u64 t; cvta.to.shared.u64 t, %1; cvt.u32.u64 %0, t; }"
        : "=r"(a) : "l"(p));
    return a;
}
__device__ __forceinline__ void cp_async16(uint32_t dst, const void* src) {
    asm volatile("cp.async.cg.shared.global [%0], [%1], 16;"
                 :: "r"(dst), "l"(src) : "memory");
}
#define CP_COMMIT() asm volatile("cp.async.commit_group;" ::: "memory")
#define CP_WAIT1()  asm volatile("cp.async.wait_group 1;" ::: "memory")

__device__ __forceinline__ void ldm_x4(uint32_t* r, uint32_t addr) {
    asm volatile("ldmatrix.sync.aligned.m8n8.x4.shared.b16 {%0,%1,%2,%3}, [%4];"
                 : "=r"(r[0]), "=r"(r[1]), "=r"(r[2]), "=r"(r[3]) : "r"(addr));
}
__device__ __forceinline__ void mma16816(float* c, const uint32_t* a,
                                         uint32_t b0, uint32_t b1) {
    asm volatile(
        "mma.sync.aligned.m16n8k16.row.col.f32.f16.f16.f32 "
        "{%0,%1,%2,%3}, {%4,%5,%6,%7}, {%8,%9}, {%0,%1,%2,%3};"
        : "+f"(c[0]), "+f"(c[1]), "+f"(c[2]), "+f"(c[3])
        : "r"(a[0]), "r"(a[1]), "r"(a[2]), "r"(a[3]), "r"(b0), "r"(b1));
}

// ===========================================================================
// Kernel 1: prep — fused trace scan + spike fp16 K-major transpose.
// Thread owns (b, 2 adjacent columns). k = b*104 + t; pads zeroed.
// Grid: (16384 + 8192) / 256 = 96 CTAs.
// ===========================================================================
__global__ void __launch_bounds__(256) prep_kernel(
    const float* __restrict__ pre_s,    // [100][32][1024]
    const float* __restrict__ post_s,   // [100][32][512]
    const float* __restrict__ pre_tr0,
    const float* __restrict__ post_tr0,
    float* __restrict__ out)
{
    const int idx = blockIdx.x * 256 + threadIdx.x;
    union U8 { __half h[8]; uint4 v; };

    if (idx < 16384) {                  // pre side: 32 * 1024 / 2
        const int n2 = idx & 511, b = idx >> 9;
        const float2* src = (const float2*)pre_s;
        const int sbase = b * 512 + n2;
        float2 tr = *(const float2*)(pre_tr0 + b * 1024 + 2 * n2);
        const size_t r0 = (size_t)(2 * n2) * K_PAD + b * TB_PAD;
        const size_t r1 = r0 + K_PAD;

        for (int g = 0; g < 12; g++) {
            float2 v[8];
            #pragma unroll
            for (int u = 0; u < 8; u++)
                v[u] = src[(size_t)(g * 8 + u) * 16384 + sbase];
            U8 t0, t1, s0, s1;
            #pragma unroll
            for (int u = 0; u < 8; u++) {
                tr.x = tr.x * DECAY + v[u].x;
                tr.y = tr.y * DECAY + v[u].y;
                t0.h[u] = __float2half(tr.x);
                t1.h[u] = __float2half(tr.y);
                s0.h[u] = __float2half(v[u].x);
                s1.h[u] = __float2half(v[u].y);
            }
            *(uint4*)(g_B0 + r0 + g * 8) = t0.v;
            *(uint4*)(g_B0 + r1 + g * 8) = t1.v;
            *(uint4*)(g_B1 + r0 + g * 8) = s0.v;
            *(uint4*)(g_B1 + r1 + g * 8) = s1.v;
        }
        {   // tail t = 96..99 + 4 zero pads
            float2 v[4];
            #pragma unroll
            for (int u = 0; u < 4; u++)
                v[u] = src[(size_t)(96 + u) * 16384 + sbase];
            U8 t0, t1, s0, s1;
            #pragma unroll
            for (int u = 0; u < 4; u++) {
                tr.x = tr.x * DECAY + v[u].x;
                tr.y = tr.y * DECAY + v[u].y;
                t0.h[u] = __float2half(tr.x);
                t1.h[u] = __float2half(tr.y);
                s0.h[u] = __float2half(v[u].x);
                s1.h[u] = __float2half(v[u].y);
            }
            #pragma unroll
            for (int u = 4; u < 8; u++) {
                t0.h[u] = t1.h[u] = s0.h[u] = s1.h[u] = __float2half(0.f);
            }
            *(uint4*)(g_B0 + r0 + 96) = t0.v;
            *(uint4*)(g_B0 + r1 + 96) = t1.v;
            *(uint4*)(g_B1 + r0 + 96) = s0.v;
            *(uint4*)(g_B1 + r1 + 96) = s1.v;
        }
        *(float2*)(out + PRETR_OFF + b * 1024 + 2 * n2) = tr;
    } else {                            // post side: 32 * 512 / 2
        const int j = idx - 16384;
        const int n2 = j & 255, b = j >> 8;
        const float2* src = (const float2*)post_s;
        const int sbase = b * 256 + n2;
        float2 tr = *(const float2*)(post_tr0 + b * 512 + 2 * n2);
        const size_t r0 = (size_t)(2 * n2) * K_PAD + b * TB_PAD;
        const size_t r1 = r0 + K_PAD;

        for (int g = 0; g < 12; g++) {
            float2 v[8];
            #pragma unroll
            for (int u = 0; u < 8; u++)
                v[u] = src[(size_t)(g * 8 + u) * 8192 + sbase];
            U8 t0, t1, s0, s1;
            #pragma unroll
            for (int u = 0; u < 8; u++) {
                tr.x = tr.x * DECAY + v[u].x;
                tr.y = tr.y * DECAY + v[u].y;
                t0.h[u] = __float2half(tr.x);
                t1.h[u] = __float2half(tr.y);
                s0.h[u] = __float2half(v[u].x);
                s1.h[u] = __float2half(v[u].y);
            }
            *(uint4*)(g_A1 + r0 + g * 8) = t0.v;
            *(uint4*)(g_A1 + r1 + g * 8) = t1.v;
            *(uint4*)(g_A0 + r0 + g * 8) = s0.v;
            *(uint4*)(g_A0 + r1 + g * 8) = s1.v;
        }
        {
            float2 v[4];
            #pragma unroll
            for (int u = 0; u < 4; u++)
                v[u] = src[(size_t)(96 + u) * 8192 + sbase];
            U8 t0, t1, s0, s1;
            #pragma unroll
            for (int u = 0; u < 4; u++) {
                tr.x = tr.x * DECAY + v[u].x;
                tr.y = tr.y * DECAY + v[u].y;
                t0.h[u] = __float2half(tr.x);
                t1.h[u] = __float2half(tr.y);
                s0.h[u] = __float2half(v[u].x);
                s1.h[u] = __float2half(v[u].y);
            }
            #pragma unroll
            for (int u = 4; u < 8; u++) {
                t0.h[u] = t1.h[u] = s0.h[u] = s1.h[u] = __float2half(0.f);
            }
            *(uint4*)(g_A1 + r0 + 96) = t0.v;
            *(uint4*)(g_A1 + r1 + 96) = t1.v;
            *(uint4*)(g_A0 + r0 + 96) = s0.v;
            *(uint4*)(g_A0 + r1 + 96) = s1.v;
        }
        *(float2*)(out + POSTTR_OFF + b * 512 + 2 * n2) = tr;
    }
}

// ===========================================================================
// Kernel 2: dual fp16 GEMM via mma.sync, 3-stage cp.async pipeline.
// grid = (32 tiles, 4): y&1 = gemm id, y>>1 = k-split. 256 threads, 8 warps
// as 4(m)x2(n), warp tile 32x64, CTA tile 128x128.
// smem: 3 stages x (A 128x(64+8 pad) + B same) halves = 110592 B.
// ===========================================================================
#define PITCH       144                  // bytes per smem row (72 halves)
#define A_STAGE     (128 * PITCH)        // 18432
#define STAGE_BYTES (2 * A_STAGE)        // 36864
#define GSMEM_TOTAL (3 * STAGE_BYTES)    // 110592

__global__ void __launch_bounds__(256, 1) gemm_kernel()
{
    extern __shared__ __align__(128) char smem[];
    const uint32_t sb = smem_u32(smem);
    const int tid = threadIdx.x, lane = tid & 31, wid = tid >> 5;
    const int mt = blockIdx.x & 3, ntb = blockIdx.x >> 2;
    const int gsel = blockIdx.y & 1, ks = blockIdx.y >> 1;

    const __half* Ag = gsel ? g_A1 : g_A0;
    const __half* Bg = gsel ? g_B1 : g_B0;
    float* Pg = gsel ? g_P1 : g_P0;
    const size_t kbase = (size_t)ks * K_PART;
    const __half* Arow = Ag + (size_t)(mt * 128) * K_PAD + kbase;
    const __half* Brow = Bg + (size_t)(ntb * 128) * K_PAD + kbase;

    // per-thread cp.async slots: 4 A rows-sub + 4 B (1024 each matrix)
    const int cprow = tid >> 1;                 // 0..127 (two subs per thread x4 it)
    auto load_stage = [&](int c) {
        const uint32_t buf = sb + (c % 3) * STAGE_BYTES;
        #pragma unroll
        for (int it = 0; it < 4; it++) {
            int slot = it * 256 + tid;          // 0..1023
            int row = slot >> 3, sub = slot & 7;
            cp_async16(buf + row * PITCH + sub * 16,
                       Arow + (size_t)row * K_PAD + c * CHUNK + sub * 8);
        }
        #pragma unroll
        for (int it = 0; it < 4; it++) {
            int slot = it * 256 + tid;
            int row = slot >> 3, sub = slot & 7;
            cp_async16(buf + A_STAGE + row * PITCH + sub * 16,
                       Brow + (size_t)row * K_PAD + c * CHUNK + sub * 8);
        }
        CP_COMMIT();
    };
    (void)cprow;

    float acc[2][8][4];
    #pragma unroll
    for (int i = 0; i < 2; i++)
        #pragma unroll
        for (int j = 0; j < 8; j++)
            #pragma unroll
            for (int r = 0; r < 4; r++) acc[i][j][r] = 0.f;

    const int m_base = (wid >> 1) * 32;
    const int n_base = (wid & 1) * 64;
    // ldmatrix lane address bases (within a stage buffer)
    const uint32_t aoff = (uint32_t)((m_base + (lane & 15)) * PITCH
                                     + (lane >> 4) * 16);
    const uint32_t boff = (uint32_t)(A_STAGE
                          + (n_base + ((lane >> 4) << 3) + (lane & 7)) * PITCH
                          + ((lane >> 3) & 1) * 16);

    load_stage(0);
    load_stage(1);

    for (int c = 0; c < NCHUNKS; c++) {
        CP_WAIT1();
        __syncthreads();
        if (c + 2 < NCHUNKS) load_stage(c + 2); else CP_COMMIT();

        const uint32_t buf = sb + (c % 3) * STAGE_BYTES;
        #pragma unroll
        for (int kk = 0; kk < 4; kk++) {
            const uint32_t k0b = kk * 32;
            uint32_t ra[2][4], rb[4][4];
            #pragma unroll
            for (int mtt = 0; mtt < 2; mtt++)
                ldm_x4(ra[mtt], buf + aoff + mtt * (16 * PITCH) + k0b);
            #pragma unroll
            for (int np = 0; np < 4; np++)
                ldm_x4(rb[np], buf + boff + np * (16 * PITCH) + k0b);
            #pragma unroll
            for (int mtt = 0; mtt < 2; mtt++)
                #pragma unroll
                for (int ntt = 0; ntt < 8; ntt++)
                    mma16816(acc[mtt][ntt], ra[mtt],
                             rb[ntt >> 1][(ntt & 1) * 2],
                             rb[ntt >> 1][(ntt & 1) * 2 + 1]);
        }
    }

    // epilogue: write fp32 partials (coalesced-ish float2 stores)
    const int gid = lane >> 2, tig = lane & 3;
    #pragma unroll
    for (int mtt = 0; mtt < 2; mtt++) {
        #pragma unroll
        for (int ntt = 0; ntt < 8; ntt++) {
            int m = mt * 128 + m_base + mtt * 16 + gid;
            int n = ntb * 128 + n_base + ntt * 8 + 2 * tig;
            float* d0 = Pg + ((size_t)ks * N_OUTPUT + m) * N_INPUT + n;
            float* d1 = Pg + ((size_t)ks * N_OUTPUT + m + 8) * N_INPUT + n;
            float2 v0; v0.x = acc[mtt][ntt][0]; v0.y = acc[mtt][ntt][1];
            float2 v1; v1.x = acc[mtt][ntt][2]; v1.y = acc[mtt][ntt][3];
            *(float2*)d0 = v0;
            *(float2*)d1 = v1;
        }
    }
}

// ===========================================================================
// Kernel 3: reduce split-K partials + soft bounds -> dw
// ===========================================================================
__global__ void __launch_bounds__(256) reduce_kernel(
    const float* __restrict__ W, float* __restrict__ dw)
{
    const int o = blockIdx.x, t = threadIdx.x;
    const size_t ro = (size_t)o * (N_INPUT / 4) + t;
    float4 s0 = make_float4(0.f, 0.f, 0.f, 0.f);
    float4 s1 = make_float4(0.f, 0.f, 0.f, 0.f);
    #pragma unroll
    for (int p = 0; p < K_SPLIT; p++) {
        float4 a = ((const float4*)g_P0)[(size_t)p * (N_OUTPUT * N_INPUT / 4) + ro];
        float4 b = ((const float4*)g_P1)[(size_t)p * (N_OUTPUT * N_INPUT / 4) + ro];
        s0.x += a.x; s0.y += a.y; s0.z += a.z; s0.w += a.w;
        s1.x += b.x; s1.y += b.y; s1.z += b.z; s1.w += b.w;
    }
    const float c1 = LR_LTP_F / (float)BATCHC;
    const float c2 = LR_LTD_F / (float)BATCHC;
    float4 w4 = ((const float4*)W)[ro];
    float4 r;
    r.x = c1 * (1.f - w4.x) * s0.x + c2 * w4.x * s1.x;
    r.y = c1 * (1.f - w4.y) * s0.y + c2 * w4.y * s1.y;
    r.z = c1 * (1.f - w4.z) * s0.z + c2 * w4.z * s1.z;
    r.w = c1 * (1.f - w4.w) * s0.w + c2 * w4.w * s1.w;
    ((float4*)dw)[ro] = r;
}

// ===========================================================================
extern "C" void kernel_launch(void* const* d_in, const int* in_sizes, int n_in,
                              void* d_out, int out_size)
{
    const float* W        = (const float*)d_in[0];
    const float* pre_s    = (const float*)d_in[1];
    const float* post_s   = (const float*)d_in[2];
    const float* pre_tr0  = (const float*)d_in[3];
    const float* post_tr0 = (const float*)d_in[4];
    float* out = (float*)d_out;
    (void)in_sizes; (void)n_in; (void)out_size;

    cudaFuncSetAttribute(gemm_kernel,
                         cudaFuncAttributeMaxDynamicSharedMemorySize, GSMEM_TOTAL);

    prep_kernel<<<96, 256>>>(pre_s, post_s, pre_tr0, post_tr0, out);
    gemm_kernel<<<dim3(32, 4), 256, GSMEM_TOTAL>>>();
    reduce_kernel<<<N_OUTPUT, 256>>>(W, out);
}